// round 6
// baseline (speedup 1.0000x reference)
#include <cuda_runtime.h>
#include <math.h>
#include <stdint.h>

// ---------------------------------------------------------------------------
// Problem constants
// ---------------------------------------------------------------------------
#define BB 2
#define CIN 64
#define COUT 96
#define TT 8
#define HH 48
#define WW 48
#define NN (TT*HH*WW)          // 18432
#define K27 27
#define CK (CIN*K27)           // 1728  (kk = k*64 + c ordering)
#define OFFC (3*K27)           // 81
#define BN_TOT (BB*NN)         // 36864
#define NTILE 128
#define NTILES (BN_TOT/NTILE)  // 288
#define KC 32
#define NCHUNK (CK/KC)         // 54

#define AS_FLOATS 8192         // 2 buf x [4ks][128][8]
#define BS_FLOATS 6144         // 2 buf x [4ks][96][8]
#define TAB_OFF   ((AS_FLOATS + BS_FLOATS) * 4)   // 57344 bytes
#define SMEM0_BYTES (TAB_OFF + 2*128*4)           // + dense table
#define SMEM1_BYTES (TAB_OFF + 2*128*8*8)         // + corner table (int2)

// ---------------------------------------------------------------------------
// Static device scratch
// ---------------------------------------------------------------------------
__device__ float g_xT[(size_t)BB * NN * CIN];     // x transposed: [b][n][c]
__device__ float g_wt_off_pad[96 * CK];           // offset weights padded+reordered
__device__ float g_wt[96 * CK];                   // conv weights reordered
__device__ float g_doff[3][(size_t)BB * K27 * NN];
__device__ float g_sum[COUT], g_sqsum[COUT];
__device__ float g_scale[COUT], g_bias[COUT];

// ---------------------------------------------------------------------------
// Helpers
// ---------------------------------------------------------------------------
__device__ __forceinline__ float to_tf32(float x) {
    uint32_t r;
    asm("cvt.rna.tf32.f32 %0, %1;" : "=r"(r) : "f"(x));
    return __uint_as_float(r);
}

__device__ __forceinline__ float4 to_tf32_4(float4 v) {
    v.x = to_tf32(v.x); v.y = to_tf32(v.y);
    v.z = to_tf32(v.z); v.w = to_tf32(v.w);
    return v;
}

__device__ __forceinline__ void mma_tf32(float d[4],
                                         uint32_t a0, uint32_t a1,
                                         uint32_t a2, uint32_t a3,
                                         uint32_t b0, uint32_t b1) {
    asm volatile(
        "mma.sync.aligned.m16n8k8.row.col.f32.tf32.tf32.f32 "
        "{%0,%1,%2,%3}, {%4,%5,%6,%7}, {%8,%9}, {%0,%1,%2,%3};"
        : "+f"(d[0]), "+f"(d[1]), "+f"(d[2]), "+f"(d[3])
        : "r"(a0), "r"(a1), "r"(a2), "r"(a3), "r"(b0), "r"(b1));
}

// ---------------------------------------------------------------------------
// Kernel: transpose x [b][c][n] -> g_xT [b][n][c]
// ---------------------------------------------------------------------------
__global__ void __launch_bounds__(256)
transpose_kernel(const float* __restrict__ x) {
    __shared__ float tile[64][33];
    int n0g = blockIdx.x * 32;
    int b = n0g >= NN;
    int nn = n0g - b * NN;
    int tx = threadIdx.x, ty = threadIdx.y;   // 32 x 8
    const float* xb = x + (size_t)b * CIN * NN;
    #pragma unroll
    for (int cc = 0; cc < 8; cc++) {
        int c = cc * 8 + ty;
        tile[c][tx] = xb[(size_t)c * NN + nn + tx];
    }
    __syncthreads();
    float* dst = g_xT + ((size_t)b * NN + nn) * CIN;
    #pragma unroll
    for (int q = 0; q < 4; q++) {
        int p = ty * 4 + q;
        dst[(size_t)p * CIN + tx]      = tile[tx][p];
        dst[(size_t)p * CIN + tx + 32] = tile[tx + 32][p];
    }
}

// ---------------------------------------------------------------------------
// Kernel: prep — reorder weights [o][c*27+k] -> [o][k*64+c], tf32-round, pad.
// ---------------------------------------------------------------------------
__global__ void prep_kernel(const float* __restrict__ w_off,
                            const float* __restrict__ w) {
    int i = blockIdx.x * blockDim.x + threadIdx.x;
    if (i < 96 * CK) {
        int o = i / CK, kk = i - o * CK;
        int k = kk >> 6, c = kk & 63;
        int src = c * K27 + k;
        g_wt[i] = to_tf32(w[o * CK + src]);
        g_wt_off_pad[i] = (o < OFFC) ? to_tf32(w_off[o * CK + src]) : 0.0f;
    }
    if (i < COUT) { g_sum[i] = 0.0f; g_sqsum[i] = 0.0f; }
}

// ---------------------------------------------------------------------------
// Fused gather + GEMM.  C[128 pos x 96 ch] per CTA, K = 1728 (27 taps x 64c).
// 256 threads = 8 warps in 4(M) x 2(N); warp tile 32 x 48.
// A tiles gathered per-chunk directly from g_xT via a per-tap table:
//   MODE 0 (dense):  table = shifted position index (or -1)
//   MODE 1 (deform): table = 8 x (corner position, trilinear weight)
// Epilogue MODE 0: +bias, tanh, scale -> g_doff.  MODE 1: -> out + BN atomics.
// ---------------------------------------------------------------------------
template <int MODE>
__global__ void __launch_bounds__(256, 2)
gemm_fused_kernel(const float* __restrict__ b_off, float* __restrict__ out) {
    extern __shared__ char smem_raw[];
    float* As = (float*)smem_raw;                       // [2][4][128][8] perm
    float* Bs = (float*)smem_raw + AS_FLOATS;           // [2][4][96][8] perm
    int*  s_base = (int*)(smem_raw + TAB_OFF);          // MODE0: [2][128]
    int2* s_tab  = (int2*)(smem_raw + TAB_OFF);         // MODE1: [2][128][8]

    int tid = threadIdx.x;
    int wid = tid >> 5, lane = tid & 31;
    int gid = lane >> 2, tig = lane & 3;
    int warp_m = wid & 3, warp_n = wid >> 2;
    int n0 = blockIdx.x * NTILE;
    int bb = n0 >= NN;                 // tile never straddles batch (NN%128==0)

    const float4* xT4 = (const float4*)g_xT;
    const float4* Bmat = (const float4*)((MODE == 0) ? g_wt_off_pad : g_wt);

    int arow = tid >> 1;   // 0..127
    int ah   = tid & 1;    // float4 parity within pairs

    // ---- table computation for one tap -------------------------------
    auto make_table = [&](int tap, int slot) {
        if (tid < 128) {
            int row = tid;
            int n = n0 - bb * NN + row;
            int t = n / (HH * WW);
            int r = n % (HH * WW);
            int y = r / WW;
            int xx = r - y * WW;
            int kt = tap / 9, ky = (tap / 3) % 3, kx = tap % 3;
            if (MODE == 0) {
                int zt = t + kt - 1, zy = y + ky - 1, zx = xx + kx - 1;
                bool valid = (zt >= 0 && zt < TT && zy >= 0 && zy < HH &&
                              zx >= 0 && zx < WW);
                s_base[slot * 128 + row] =
                    valid ? (bb * NN + (zt * HH + zy) * WW + zx) : -1;
            } else {
                size_t oidx = (size_t)(bb * K27 + tap) * NN + n;
                float pt = (float)(t + kt - 1) + g_doff[0][oidx];
                float py = (float)(y + ky - 1) + g_doff[1][oidx];
                float px = (float)(xx + kx - 1) + g_doff[2][oidx];
                float tf = floorf(pt), yf = floorf(py), xf = floorf(px);
                int it = (int)tf, iy = (int)yf, ix = (int)xf;
                float ft = pt - tf, fy = py - yf, fx = px - xf;
                #pragma unroll
                for (int j = 0; j < 8; j++) {
                    int at = (j >> 2) & 1, ay = (j >> 1) & 1, ax = j & 1;
                    int ti = it + at, yi = iy + ay, xi = ix + ax;
                    bool valid = (ti >= 0 && ti < TT && yi >= 0 && yi < HH &&
                                  xi >= 0 && xi < WW);
                    float wv = (at ? ft : 1.0f - ft) * (ay ? fy : 1.0f - fy)
                             * (ax ? fx : 1.0f - fx);
                    int pidx = valid ? (bb * NN + (ti * HH + yi) * WW + xi)
                                     : bb * NN;
                    s_tab[(slot * 128 + row) * 8 + j] =
                        make_int2(pidx, __float_as_int(valid ? wv : 0.0f));
                }
            }
        }
    };

    // ---- staging -------------------------------------------------------
    float4 pa[4];
    float4 pb[3];

    auto fetch = [&](int chunk) {
        int chalf = chunk & 1;
        int slot = (chunk >> 1) & 1;
        if (MODE == 0) {
            int idx = s_base[slot * 128 + arow];
            const float4* base = xT4 + (size_t)max(idx, 0) * 16 + chalf * 8 + ah;
            #pragma unroll
            for (int i = 0; i < 4; i++) {
                float4 v = make_float4(0.f, 0.f, 0.f, 0.f);
                if (idx >= 0) v = __ldg(base + i * 2);
                pa[i] = v;
            }
        } else {
            int2 tcw[8];
            #pragma unroll
            for (int j = 0; j < 8; j++)
                tcw[j] = s_tab[(slot * 128 + arow) * 8 + j];
            #pragma unroll
            for (int i = 0; i < 4; i++) {
                float4 acc = make_float4(0.f, 0.f, 0.f, 0.f);
                #pragma unroll
                for (int j = 0; j < 8; j++) {
                    float wv = __int_as_float(tcw[j].y);
                    float4 v = __ldg(xT4 + (size_t)tcw[j].x * 16
                                     + chalf * 8 + i * 2 + ah);
                    acc.x = fmaf(wv, v.x, acc.x);
                    acc.y = fmaf(wv, v.y, acc.y);
                    acc.z = fmaf(wv, v.z, acc.z);
                    acc.w = fmaf(wv, v.w, acc.w);
                }
                pa[i] = acc;
            }
        }
        #pragma unroll
        for (int i = 0; i < 3; i++) {
            int j = tid + i * 256;
            pb[i] = __ldg(Bmat + (size_t)(j >> 3) * (CK / 4)
                          + chunk * 8 + (j & 7));
        }
    };

    auto store_smem = [&](int buf) {
        #pragma unroll
        for (int i = 0; i < 4; i++) {
            // c4 = i*2 + ah ; ks = i ; lanebit = ah
            float* p = As + buf * 4096 + i * 1024 + arow * 8 + ah;
            float4 v = to_tf32_4(pa[i]);
            p[0] = v.x; p[2] = v.y; p[4] = v.z; p[6] = v.w;
        }
        #pragma unroll
        for (int i = 0; i < 3; i++) {
            int j = tid + i * 256;
            int row = j >> 3, c4 = j & 7;
            float* p = Bs + buf * 3072 + (c4 >> 1) * 768 + row * 8 + (c4 & 1);
            p[0] = pb[i].x; p[2] = pb[i].y; p[4] = pb[i].z; p[6] = pb[i].w;
        }
    };

    // ---- accumulators --------------------------------------------------
    float d[2][6][4];
    #pragma unroll
    for (int mt = 0; mt < 2; mt++)
        #pragma unroll
        for (int nt = 0; nt < 6; nt++)
            #pragma unroll
            for (int q = 0; q < 4; q++) d[mt][nt][q] = 0.0f;

    // ---- prologue ------------------------------------------------------
    make_table(0, 0);
    make_table(1, 1);
    __syncthreads();
    fetch(0); store_smem(0); fetch(1);
    __syncthreads();

    // ---- main loop -----------------------------------------------------
    for (int chunk = 0; chunk < NCHUNK; chunk++) {
        int buf = chunk & 1;
        const float2* Ap = (const float2*)(As + buf * 4096);
        const float2* Bp = (const float2*)(Bs + buf * 3072);
        #pragma unroll
        for (int ks = 0; ks < 4; ks++) {
            uint32_t af[2][4], bf[6][2];
            #pragma unroll
            for (int mt = 0; mt < 2; mt++) {
                int row = warp_m * 32 + mt * 16 + gid;
                float2 a02 = Ap[ks * 512 + row * 4 + tig];
                float2 a13 = Ap[ks * 512 + (row + 8) * 4 + tig];
                af[mt][0] = __float_as_uint(a02.x);
                af[mt][1] = __float_as_uint(a13.x);
                af[mt][2] = __float_as_uint(a02.y);
                af[mt][3] = __float_as_uint(a13.y);
            }
            #pragma unroll
            for (int nt = 0; nt < 6; nt++) {
                int col = warp_n * 48 + nt * 8 + gid;
                float2 b01 = Bp[ks * 384 + col * 4 + tig];
                bf[nt][0] = __float_as_uint(b01.x);
                bf[nt][1] = __float_as_uint(b01.y);
            }
            #pragma unroll
            for (int mt = 0; mt < 2; mt++)
                #pragma unroll
                for (int nt = 0; nt < 6; nt++)
                    mma_tf32(d[mt][nt], af[mt][0], af[mt][1], af[mt][2],
                             af[mt][3], bf[nt][0], bf[nt][1]);
        }
        if (chunk & 1) {
            int ntap = (chunk + 3) >> 1;
            if (ntap < K27) make_table(ntap, ntap & 1);
        }
        if (chunk + 1 < NCHUNK) store_smem((chunk + 1) & 1);
        if (chunk + 2 < NCHUNK) fetch(chunk + 2);
        __syncthreads();
    }

    // ---- epilogue ------------------------------------------------------
    #pragma unroll
    for (int mt = 0; mt < 2; mt++) {
        #pragma unroll
        for (int half = 0; half < 2; half++) {
            int row = warp_m * 32 + mt * 16 + half * 8 + gid;
            int n = n0 - bb * NN + row;
            #pragma unroll
            for (int nt = 0; nt < 6; nt++) {
                #pragma unroll
                for (int e = 0; e < 2; e++) {
                    int col = warp_n * 48 + nt * 8 + tig * 2 + e;
                    float v = d[mt][nt][half * 2 + e];
                    if (MODE == 0) {
                        if (col < OFFC) {
                            int axis = col / K27, kk = col - axis * K27;
                            float sc = axis ? 2.0f : 1.0f;
                            float o = tanhf(v + __ldg(b_off + col)) * sc;
                            g_doff[axis][(size_t)(bb * K27 + kk) * NN + n] = o;
                        }
                    } else {
                        out[(size_t)(bb * COUT + col) * NN + n] = v;
                    }
                }
            }
        }
    }

    // ---- fused BN stats (MODE 1) ---------------------------------------
    if (MODE == 1) {
        #pragma unroll
        for (int nt = 0; nt < 6; nt++) {
            #pragma unroll
            for (int e = 0; e < 2; e++) {
                float s = 0.0f, q = 0.0f;
                #pragma unroll
                for (int mt = 0; mt < 2; mt++)
                    #pragma unroll
                    for (int half = 0; half < 2; half++) {
                        float v = d[mt][nt][half * 2 + e];
                        s += v; q += v * v;
                    }
                #pragma unroll
                for (int off = 16; off >= 4; off >>= 1) {
                    s += __shfl_down_sync(0xffffffffu, s, off);
                    q += __shfl_down_sync(0xffffffffu, q, off);
                }
                if (lane < 4) {
                    int col = warp_n * 48 + nt * 8 + tig * 2 + e;
                    atomicAdd(&g_sum[col], s);
                    atomicAdd(&g_sqsum[col], q);
                }
            }
        }
    }
}

// ---------------------------------------------------------------------------
// BN finalize + apply
// ---------------------------------------------------------------------------
__global__ void bn_finalize_kernel(const float* __restrict__ gamma,
                                   const float* __restrict__ beta) {
    int c = threadIdx.x;
    if (c < COUT) {
        float cnt = (float)(BB * NN);
        float mean = g_sum[c] / cnt;
        float var = g_sqsum[c] / cnt - mean * mean;
        float inv = rsqrtf(var + 1e-5f);
        float sc = gamma[c] * inv;
        g_scale[c] = sc;
        g_bias[c] = beta[c] - mean * sc;
    }
}

__global__ void __launch_bounds__(256)
bn_apply_kernel(float* __restrict__ out) {
    int i4 = blockIdx.x * blockDim.x + threadIdx.x;
    const int TOT4 = BB * COUT * NN / 4;
    if (i4 < TOT4) {
        int c = (i4 / (NN / 4)) % COUT;
        float sc = g_scale[c], bi = g_bias[c];
        float4 v = reinterpret_cast<float4*>(out)[i4];
        v.x = fmaxf(fmaf(v.x, sc, bi), 0.0f);
        v.y = fmaxf(fmaf(v.y, sc, bi), 0.0f);
        v.z = fmaxf(fmaf(v.z, sc, bi), 0.0f);
        v.w = fmaxf(fmaf(v.w, sc, bi), 0.0f);
        reinterpret_cast<float4*>(out)[i4] = v;
    }
}

// ---------------------------------------------------------------------------
extern "C" void kernel_launch(void* const* d_in, const int* in_sizes, int n_in,
                              void* d_out, int out_size) {
    const float* x     = (const float*)d_in[0];
    const float* w_off = (const float*)d_in[1];
    const float* b_off = (const float*)d_in[2];
    const float* w     = (const float*)d_in[3];
    const float* gamma = (const float*)d_in[4];
    const float* beta  = (const float*)d_in[5];
    float* out = (float*)d_out;

    cudaFuncSetAttribute(gemm_fused_kernel<0>,
                         cudaFuncAttributeMaxDynamicSharedMemorySize,
                         SMEM0_BYTES);
    cudaFuncSetAttribute(gemm_fused_kernel<1>,
                         cudaFuncAttributeMaxDynamicSharedMemorySize,
                         SMEM1_BYTES);

    transpose_kernel<<<BN_TOT / 32, dim3(32, 8)>>>(x);
    prep_kernel<<<(96 * CK + 255) / 256, 256>>>(w_off, w);

    gemm_fused_kernel<0><<<NTILES, 256, SMEM0_BYTES>>>(b_off, nullptr);
    gemm_fused_kernel<1><<<NTILES, 256, SMEM1_BYTES>>>(nullptr, out);

    bn_finalize_kernel<<<1, 128>>>(gamma, beta);

    const int TOT4 = BB * COUT * NN / 4;
    bn_apply_kernel<<<(TOT4 + 255) / 256, 256>>>(out);
}

// round 7
// speedup vs baseline: 1.7217x; 1.7217x over previous
#include <cuda_runtime.h>
#include <math.h>
#include <stdint.h>

// ---------------------------------------------------------------------------
// Problem constants
// ---------------------------------------------------------------------------
#define BB 2
#define CIN 64
#define COUT 96
#define TT 8
#define HH 48
#define WW 48
#define NN (TT*HH*WW)          // 18432
#define K27 27
#define CK (CIN*K27)           // 1728  (kk = k*64 + c ordering)
#define OFFC (3*K27)           // 81
#define BN_TOT (BB*NN)         // 36864
#define NTILE 128
#define NTILES (BN_TOT/NTILE)  // 288
#define NCHUNK (CK/32)         // 54 chunks of 32 k-floats

#define A_STAGE_BYTES 16384    // 128 rows x 128B
#define B_STAGE_BYTES 12288    // 96 rows x 128B
#define STAGE_BYTES   (A_STAGE_BYTES + B_STAGE_BYTES)   // 28672
#define NSTAGE 3
#define SMEM_BYTES (NSTAGE * STAGE_BYTES)               // 86016

// ---------------------------------------------------------------------------
// Static device scratch
// ---------------------------------------------------------------------------
__device__ float g_xT[(size_t)BB * NN * CIN];     // x transposed+tf32: [b][n][c]
__device__ float g_cols[(size_t)BN_TOT * CK];     // deform im2col [bn][k*64+c]
__device__ float g_wt_off_pad[96 * CK];           // offset weights padded+reordered
__device__ float g_wt[96 * CK];                   // conv weights reordered
__device__ float g_doff[3][(size_t)BB * K27 * NN];
__device__ float g_sum[COUT], g_sqsum[COUT];
__device__ float g_scale[COUT], g_bias[COUT];

// ---------------------------------------------------------------------------
// Helpers
// ---------------------------------------------------------------------------
__device__ __forceinline__ float to_tf32(float x) {
    uint32_t r;
    asm("cvt.rna.tf32.f32 %0, %1;" : "=r"(r) : "f"(x));
    return __uint_as_float(r);
}

__device__ __forceinline__ float4 to_tf32_4(float4 v) {
    v.x = to_tf32(v.x); v.y = to_tf32(v.y);
    v.z = to_tf32(v.z); v.w = to_tf32(v.w);
    return v;
}

__device__ __forceinline__ uint32_t smem_u32(const void* p) {
    uint32_t a;
    asm("{ .reg .u64 t; cvta.to.shared.u64 t, %1; cvt.u32.u64 %0, t; }"
        : "=r"(a) : "l"(p));
    return a;
}

__device__ __forceinline__ void cp16(uint32_t dst, const void* src, int sz) {
    asm volatile("cp.async.cg.shared.global [%0], [%1], 16, %2;"
                 :: "r"(dst), "l"(src), "r"(sz) : "memory");
}

#define CP_COMMIT() asm volatile("cp.async.commit_group;" ::: "memory")
#define CP_WAIT1()  asm volatile("cp.async.wait_group 1;" ::: "memory")
#define CP_WAIT0()  asm volatile("cp.async.wait_group 0;" ::: "memory")

__device__ __forceinline__ void ldsm_x4(uint32_t r[4], uint32_t addr) {
    asm volatile("ldmatrix.sync.aligned.m8n8.x4.shared.b16 {%0,%1,%2,%3}, [%4];"
                 : "=r"(r[0]), "=r"(r[1]), "=r"(r[2]), "=r"(r[3]) : "r"(addr));
}

__device__ __forceinline__ void ldsm_x2(uint32_t r[2], uint32_t addr) {
    asm volatile("ldmatrix.sync.aligned.m8n8.x2.shared.b16 {%0,%1}, [%2];"
                 : "=r"(r[0]), "=r"(r[1]) : "r"(addr));
}

__device__ __forceinline__ void mma_tf32(float d[4],
                                         const uint32_t a[4],
                                         const uint32_t b[2]) {
    asm volatile(
        "mma.sync.aligned.m16n8k8.row.col.f32.tf32.tf32.f32 "
        "{%0,%1,%2,%3}, {%4,%5,%6,%7}, {%8,%9}, {%0,%1,%2,%3};"
        : "+f"(d[0]), "+f"(d[1]), "+f"(d[2]), "+f"(d[3])
        : "r"(a[0]), "r"(a[1]), "r"(a[2]), "r"(a[3]), "r"(b[0]), "r"(b[1]));
}

// ---------------------------------------------------------------------------
// Kernel: transpose x [b][c][n] -> g_xT [b][n][c], rounded to tf32
// ---------------------------------------------------------------------------
__global__ void __launch_bounds__(256)
transpose_kernel(const float* __restrict__ x) {
    __shared__ float tile[64][33];
    int n0g = blockIdx.x * 32;
    int b = n0g >= NN;
    int nn = n0g - b * NN;
    int tx = threadIdx.x, ty = threadIdx.y;   // 32 x 8
    const float* xb = x + (size_t)b * CIN * NN;
    #pragma unroll
    for (int cc = 0; cc < 8; cc++) {
        int c = cc * 8 + ty;
        tile[c][tx] = to_tf32(xb[(size_t)c * NN + nn + tx]);
    }
    __syncthreads();
    float* dst = g_xT + ((size_t)b * NN + nn) * CIN;
    #pragma unroll
    for (int q = 0; q < 4; q++) {
        int p = ty * 4 + q;
        dst[(size_t)p * CIN + tx]      = tile[tx][p];
        dst[(size_t)p * CIN + tx + 32] = tile[tx + 32][p];
    }
}

// ---------------------------------------------------------------------------
// Kernel: prep — reorder weights [o][c*27+k] -> [o][k*64+c], tf32-round, pad.
// ---------------------------------------------------------------------------
__global__ void prep_kernel(const float* __restrict__ w_off,
                            const float* __restrict__ w) {
    int i = blockIdx.x * blockDim.x + threadIdx.x;
    if (i < 96 * CK) {
        int o = i / CK, kk = i - o * CK;
        int k = kk >> 6, c = kk & 63;
        int src = c * K27 + k;
        g_wt[i] = to_tf32(w[o * CK + src]);
        g_wt_off_pad[i] = (o < OFFC) ? to_tf32(w_off[o * CK + src]) : 0.0f;
    }
    if (i < COUT) { g_sum[i] = 0.0f; g_sqsum[i] = 0.0f; }
}

// ---------------------------------------------------------------------------
// Kernel: deformable (trilinear) im2col gather from g_xT -> g_cols
// ---------------------------------------------------------------------------
__global__ void __launch_bounds__(128)
deform_gather_kernel() {
    int bn = blockIdx.x;
    int b = bn >= NN;
    int n = bn - b * NN;
    int t = n / (HH * WW);
    int y = (n / WW) % HH;
    int xx = n % WW;

    __shared__ int   s_idx[K27][8];
    __shared__ float s_w[K27][8];

    int tid = threadIdx.x;
    if (tid < K27) {
        int k = tid;
        int kt = k / 9, ky = (k / 3) % 3, kx = k % 3;
        size_t oidx = (size_t)(b * K27 + k) * NN + n;
        float pt = (float)(t + kt - 1) + g_doff[0][oidx];
        float py = (float)(y + ky - 1) + g_doff[1][oidx];
        float px = (float)(xx + kx - 1) + g_doff[2][oidx];
        float tf = floorf(pt), yf = floorf(py), xf = floorf(px);
        int it = (int)tf, iy = (int)yf, ix = (int)xf;
        float ft = pt - tf, fy = py - yf, fx = px - xf;
        #pragma unroll
        for (int j = 0; j < 8; j++) {
            int at = (j >> 2) & 1, ay = (j >> 1) & 1, ax = j & 1;
            int ti = it + at, yi = iy + ay, xi = ix + ax;
            bool valid = (ti >= 0 && ti < TT && yi >= 0 && yi < HH &&
                          xi >= 0 && xi < WW);
            float wv = (at ? ft : 1.0f - ft) * (ay ? fy : 1.0f - fy)
                     * (ax ? fx : 1.0f - fx);
            s_w[k][j]   = valid ? wv : 0.0f;
            s_idx[k][j] = valid ? (ti * HH + yi) * WW + xi : 0;
        }
    }
    __syncthreads();

    const float4* xb4 = (const float4*)(g_xT + (size_t)b * NN * CIN);
    float4* dst = (float4*)(g_cols + (size_t)bn * CK);
    #pragma unroll
    for (int i = 0; i < 4; i++) {
        int u = tid + i * 128;
        if (u < K27 * 16) {
            int k = u >> 4, c4 = u & 15;
            float4 acc = make_float4(0.f, 0.f, 0.f, 0.f);
            #pragma unroll
            for (int j = 0; j < 8; j++) {
                float wv = s_w[k][j];
                float4 v = __ldg(xb4 + (size_t)s_idx[k][j] * 16 + c4);
                acc.x = fmaf(wv, v.x, acc.x);
                acc.y = fmaf(wv, v.y, acc.y);
                acc.z = fmaf(wv, v.z, acc.z);
                acc.w = fmaf(wv, v.w, acc.w);
            }
            dst[k * 16 + c4] = to_tf32_4(acc);
        }
    }
}

// ---------------------------------------------------------------------------
// GEMM: C[128 pos x 96 ch] per CTA, K=1728, tf32 mma.sync.
// cp.async 3-stage pipeline, XOR-swizzled smem, ldmatrix fragments.
// 256 threads = 8 warps 4(M) x 2(N); warp tile 32 x 48.
// MODE 0: A gathered from g_xT via dense tap shift (cp.async zfill);
//         B = g_wt_off_pad; epilogue tanh -> g_doff.
// MODE 1: A = g_cols (contiguous); B = g_wt; epilogue -> out + BN atomics.
// ---------------------------------------------------------------------------
template <int MODE>
__global__ void __launch_bounds__(256, 2)
gemm_cp_kernel(const float* __restrict__ b_off, float* __restrict__ out) {
    extern __shared__ char smem_raw[];
    uint32_t smem_base = smem_u32(smem_raw);

    int tid = threadIdx.x;
    int wid = tid >> 5, lane = tid & 31;
    int gid = lane >> 2, tig = lane & 3;
    int warp_m = wid & 3, warp_n = wid >> 2;
    int n0 = blockIdx.x * NTILE;
    int bb = n0 >= NN;

    const float* Bmat = (MODE == 0) ? g_wt_off_pad : g_wt;

    // staging coordinates: granule g = tid + i*256 -> row g>>3, c4 = tid&7
    int c4s = tid & 7;
    int row0 = tid >> 3;

    // MODE 0: precompute (t,y,x) for this thread's 4 A rows
    int rt_[4], ry_[4], rx_[4];
    if (MODE == 0) {
        #pragma unroll
        for (int i = 0; i < 4; i++) {
            int n = n0 - bb * NN + row0 + i * 32;
            rt_[i] = n / (HH * WW);
            int r = n % (HH * WW);
            ry_[i] = r / WW;
            rx_[i] = r - ry_[i] * WW;
        }
    }

    auto issue = [&](int chunk) {
        uint32_t stage = (uint32_t)(chunk % NSTAGE) * STAGE_BYTES;
        uint32_t Ab = smem_base + stage;
        uint32_t Bb = Ab + A_STAGE_BYTES;
        // A granules
        if (MODE == 0) {
            int tap = chunk >> 1;
            int kt = tap / 9;
            int kr = tap - kt * 9;
            int ky = kr / 3, kx = kr - (kr / 3) * 3;
            int chalf = (chunk & 1) * 32;
            #pragma unroll
            for (int i = 0; i < 4; i++) {
                int row = row0 + i * 32;
                int zt = rt_[i] + kt - 1, zy = ry_[i] + ky - 1,
                    zx = rx_[i] + kx - 1;
                bool valid = (zt >= 0 && zt < TT && zy >= 0 && zy < HH &&
                              zx >= 0 && zx < WW);
                int idx = valid ? (bb * NN + (zt * HH + zy) * WW + zx) : 0;
                const float* src = g_xT + (size_t)idx * CIN + chalf + c4s * 4;
                uint32_t dst = Ab + (row << 7) + ((c4s ^ (row & 7)) << 4);
                cp16(dst, src, valid ? 16 : 0);
            }
        } else {
            #pragma unroll
            for (int i = 0; i < 4; i++) {
                int row = row0 + i * 32;
                const float* src = g_cols + (size_t)(n0 + row) * CK
                                 + chunk * 32 + c4s * 4;
                uint32_t dst = Ab + (row << 7) + ((c4s ^ (row & 7)) << 4);
                cp16(dst, src, 16);
            }
        }
        // B granules (96 rows x 8 granules = 768; 3 per thread)
        #pragma unroll
        for (int i = 0; i < 3; i++) {
            int col = row0 + i * 32;
            const float* src = Bmat + (size_t)col * CK + chunk * 32 + c4s * 4;
            uint32_t dst = Bb + (col << 7) + ((c4s ^ (col & 7)) << 4);
            cp16(dst, src, 16);
        }
        CP_COMMIT();
    };

    // accumulators: 2 M-blocks x 6 N-blocks
    float d[2][6][4];
    #pragma unroll
    for (int mt = 0; mt < 2; mt++)
        #pragma unroll
        for (int nt = 0; nt < 6; nt++)
            #pragma unroll
            for (int q = 0; q < 4; q++) d[mt][nt][q] = 0.0f;

    // fragment-load lane geometry (fixed per thread)
    int a_row_lo = (lane & 7) + ((lane >> 3) & 1) * 8;  // within 16-row block
    int a_hi = lane >> 4;                               // c4 low bit
    int b_col = warp_n * 48 + (lane & 7);               // + nt*8
    int b_hi = (lane >> 3) & 1;

    issue(0);
    issue(1);

    for (int chunk = 0; chunk < NCHUNK; chunk++) {
        if (chunk < NCHUNK - 1) { CP_WAIT1(); } else { CP_WAIT0(); }
        __syncthreads();
        if (chunk + 2 < NCHUNK) issue(chunk + 2);

        uint32_t stage = (uint32_t)(chunk % NSTAGE) * STAGE_BYTES;
        uint32_t Ab = smem_base + stage;
        uint32_t Bb = Ab + A_STAGE_BYTES;

        #pragma unroll
        for (int ks = 0; ks < 4; ks++) {
            uint32_t af[2][4], bf[6][2];
            #pragma unroll
            for (int mt = 0; mt < 2; mt++) {
                int row = warp_m * 32 + mt * 16 + a_row_lo;
                int c4 = 2 * ks + a_hi;
                uint32_t addr = Ab + (row << 7) + ((c4 ^ (row & 7)) << 4);
                ldsm_x4(af[mt], addr);
            }
            #pragma unroll
            for (int nt = 0; nt < 6; nt++) {
                int col = b_col + nt * 8;
                int c4 = 2 * ks + b_hi;
                uint32_t addr = Bb + (col << 7) + ((c4 ^ (col & 7)) << 4);
                ldsm_x2(bf[nt], addr);
            }
            #pragma unroll
            for (int mt = 0; mt < 2; mt++)
                #pragma unroll
                for (int nt = 0; nt < 6; nt++)
                    mma_tf32(d[mt][nt], af[mt], bf[nt]);
        }
        __syncthreads();
    }

    // ---- epilogue ------------------------------------------------------
    #pragma unroll
    for (int mt = 0; mt < 2; mt++) {
        #pragma unroll
        for (int half = 0; half < 2; half++) {
            int row = warp_m * 32 + mt * 16 + half * 8 + gid;
            int n = n0 - bb * NN + row;
            #pragma unroll
            for (int nt = 0; nt < 6; nt++) {
                #pragma unroll
                for (int e = 0; e < 2; e++) {
                    int col = warp_n * 48 + nt * 8 + tig * 2 + e;
                    float v = d[mt][nt][half * 2 + e];
                    if (MODE == 0) {
                        if (col < OFFC) {
                            int axis = col / K27, kk = col - axis * K27;
                            float sc = axis ? 2.0f : 1.0f;
                            float o = tanhf(v + __ldg(b_off + col)) * sc;
                            g_doff[axis][(size_t)(bb * K27 + kk) * NN + n] = o;
                        }
                    } else {
                        out[(size_t)(bb * COUT + col) * NN + n] = v;
                    }
                }
            }
        }
    }

    // ---- fused BN stats (MODE 1) ---------------------------------------
    if (MODE == 1) {
        #pragma unroll
        for (int nt = 0; nt < 6; nt++) {
            #pragma unroll
            for (int e = 0; e < 2; e++) {
                float s = 0.0f, q = 0.0f;
                #pragma unroll
                for (int mt = 0; mt < 2; mt++)
                    #pragma unroll
                    for (int half = 0; half < 2; half++) {
                        float v = d[mt][nt][half * 2 + e];
                        s += v; q += v * v;
                    }
                #pragma unroll
                for (int off = 16; off >= 4; off >>= 1) {
                    s += __shfl_down_sync(0xffffffffu, s, off);
                    q += __shfl_down_sync(0xffffffffu, q, off);
                }
                if (lane < 4) {
                    int col = warp_n * 48 + nt * 8 + tig * 2 + e;
                    atomicAdd(&g_sum[col], s);
                    atomicAdd(&g_sqsum[col], q);
                }
            }
        }
    }
}

// ---------------------------------------------------------------------------
// BN finalize + apply
// ---------------------------------------------------------------------------
__global__ void bn_finalize_kernel(const float* __restrict__ gamma,
                                   const float* __restrict__ beta) {
    int c = threadIdx.x;
    if (c < COUT) {
        float cnt = (float)(BB * NN);
        float mean = g_sum[c] / cnt;
        float var = g_sqsum[c] / cnt - mean * mean;
        float inv = rsqrtf(var + 1e-5f);
        float sc = gamma[c] * inv;
        g_scale[c] = sc;
        g_bias[c] = beta[c] - mean * sc;
    }
}

__global__ void __launch_bounds__(256)
bn_apply_kernel(float* __restrict__ out) {
    int i4 = blockIdx.x * blockDim.x + threadIdx.x;
    const int TOT4 = BB * COUT * NN / 4;
    if (i4 < TOT4) {
        int c = (i4 / (NN / 4)) % COUT;
        float sc = g_scale[c], bi = g_bias[c];
        float4 v = reinterpret_cast<float4*>(out)[i4];
        v.x = fmaxf(fmaf(v.x, sc, bi), 0.0f);
        v.y = fmaxf(fmaf(v.y, sc, bi), 0.0f);
        v.z = fmaxf(fmaf(v.z, sc, bi), 0.0f);
        v.w = fmaxf(fmaf(v.w, sc, bi), 0.0f);
        reinterpret_cast<float4*>(out)[i4] = v;
    }
}

// ---------------------------------------------------------------------------
extern "C" void kernel_launch(void* const* d_in, const int* in_sizes, int n_in,
                              void* d_out, int out_size) {
    const float* x     = (const float*)d_in[0];
    const float* w_off = (const float*)d_in[1];
    const float* b_off = (const float*)d_in[2];
    const float* w     = (const float*)d_in[3];
    const float* gamma = (const float*)d_in[4];
    const float* beta  = (const float*)d_in[5];
    float* out = (float*)d_out;

    cudaFuncSetAttribute(gemm_cp_kernel<0>,
                         cudaFuncAttributeMaxDynamicSharedMemorySize,
                         SMEM_BYTES);
    cudaFuncSetAttribute(gemm_cp_kernel<1>,
                         cudaFuncAttributeMaxDynamicSharedMemorySize,
                         SMEM_BYTES);

    transpose_kernel<<<BN_TOT / 32, dim3(32, 8)>>>(x);
    prep_kernel<<<(96 * CK + 255) / 256, 256>>>(w_off, w);

    gemm_cp_kernel<0><<<NTILES, 256, SMEM_BYTES>>>(b_off, nullptr);
    deform_gather_kernel<<<BN_TOT, 128>>>();
    gemm_cp_kernel<1><<<NTILES, 256, SMEM_BYTES>>>(nullptr, out);

    bn_finalize_kernel<<<1, 128>>>(gamma, beta);

    const int TOT4 = BB * COUT * NN / 4;
    bn_apply_kernel<<<(TOT4 + 255) / 256, 256>>>(out);
}

// round 8
// speedup vs baseline: 2.7069x; 1.5722x over previous
#include <cuda_runtime.h>
#include <cuda_fp16.h>
#include <math.h>
#include <stdint.h>

// ---------------------------------------------------------------------------
// Problem constants
// ---------------------------------------------------------------------------
#define BB 2
#define CIN 64
#define COUT 96
#define TT 8
#define HH 48
#define WW 48
#define NN (TT*HH*WW)          // 18432
#define K27 27
#define CK (CIN*K27)           // 1728  (kk = k*64 + c ordering)
#define OFFC (3*K27)           // 81
#define BN_TOT (BB*NN)         // 36864
#define NTILE 128
#define NTILES (BN_TOT/NTILE)  // 288
#define NCHUNK K27             // 27 chunks of 64 k-halfs (one tap each)

#define A_STAGE_BYTES 16384    // 128 rows x 128B
#define B_STAGE_BYTES 12288    // 96 rows x 128B
#define STAGE_BYTES   (A_STAGE_BYTES + B_STAGE_BYTES)   // 28672
#define NSTAGE 3
#define SMEM_BYTES (NSTAGE * STAGE_BYTES)               // 86016

// ---------------------------------------------------------------------------
// Static device scratch (all fp16 data paths)
// ---------------------------------------------------------------------------
__device__ __half g_xTh[(size_t)BB * NN * CIN];    // x transposed fp16 [b][n][c]
__device__ __half g_colsh[(size_t)BN_TOT * CK];    // deform im2col fp16
__device__ __half g_wt_off_h[96 * CK];             // offset weights fp16 padded
__device__ __half g_wth[96 * CK];                  // conv weights fp16
__device__ float g_doff[3][(size_t)BB * K27 * NN];
__device__ float g_sum[COUT], g_sqsum[COUT];
__device__ float g_scale[COUT], g_bias[COUT];

// ---------------------------------------------------------------------------
// Helpers
// ---------------------------------------------------------------------------
__device__ __forceinline__ uint32_t smem_u32(const void* p) {
    uint32_t a;
    asm("{ .reg .u64 t; cvta.to.shared.u64 t, %1; cvt.u32.u64 %0, t; }"
        : "=r"(a) : "l"(p));
    return a;
}

__device__ __forceinline__ void cp16(uint32_t dst, const void* src, int sz) {
    asm volatile("cp.async.cg.shared.global [%0], [%1], 16, %2;"
                 :: "r"(dst), "l"(src), "r"(sz) : "memory");
}

#define CP_COMMIT() asm volatile("cp.async.commit_group;" ::: "memory")
#define CP_WAIT1()  asm volatile("cp.async.wait_group 1;" ::: "memory")
#define CP_WAIT0()  asm volatile("cp.async.wait_group 0;" ::: "memory")

__device__ __forceinline__ void ldsm_x4(uint32_t r[4], uint32_t addr) {
    asm volatile("ldmatrix.sync.aligned.m8n8.x4.shared.b16 {%0,%1,%2,%3}, [%4];"
                 : "=r"(r[0]), "=r"(r[1]), "=r"(r[2]), "=r"(r[3]) : "r"(addr));
}

__device__ __forceinline__ void ldsm_x2(uint32_t r[2], uint32_t addr) {
    asm volatile("ldmatrix.sync.aligned.m8n8.x2.shared.b16 {%0,%1}, [%2];"
                 : "=r"(r[0]), "=r"(r[1]) : "r"(addr));
}

__device__ __forceinline__ void mma_f16(float d[4],
                                        const uint32_t a[4],
                                        const uint32_t b[2]) {
    asm volatile(
        "mma.sync.aligned.m16n8k16.row.col.f32.f16.f16.f32 "
        "{%0,%1,%2,%3}, {%4,%5,%6,%7}, {%8,%9}, {%0,%1,%2,%3};"
        : "+f"(d[0]), "+f"(d[1]), "+f"(d[2]), "+f"(d[3])
        : "r"(a[0]), "r"(a[1]), "r"(a[2]), "r"(a[3]), "r"(b[0]), "r"(b[1]));
}

// ---------------------------------------------------------------------------
// Kernel: transpose x [b][c][n] -> g_xTh [b][n][c] (fp16)
// ---------------------------------------------------------------------------
__global__ void __launch_bounds__(256)
transpose_kernel(const float* __restrict__ x) {
    __shared__ float tile[64][33];
    int n0g = blockIdx.x * 32;
    int b = n0g >= NN;
    int nn = n0g - b * NN;
    int tx = threadIdx.x, ty = threadIdx.y;   // 32 x 8
    const float* xb = x + (size_t)b * CIN * NN;
    #pragma unroll
    for (int cc = 0; cc < 8; cc++) {
        int c = cc * 8 + ty;
        tile[c][tx] = xb[(size_t)c * NN + nn + tx];
    }
    __syncthreads();
    __half2* dst = (__half2*)(g_xTh + ((size_t)b * NN + nn) * CIN);
    #pragma unroll
    for (int q = 0; q < 4; q++) {
        int p = ty * 4 + q;
        dst[p * 32 + tx] =
            __floats2half2_rn(tile[2 * tx][p], tile[2 * tx + 1][p]);
    }
}

// ---------------------------------------------------------------------------
// Kernel: prep — reorder weights [o][c*27+k] -> [o][k*64+c], fp16, pad.
// ---------------------------------------------------------------------------
__global__ void prep_kernel(const float* __restrict__ w_off,
                            const float* __restrict__ w) {
    int i = blockIdx.x * blockDim.x + threadIdx.x;
    if (i < 96 * CK) {
        int o = i / CK, kk = i - o * CK;
        int k = kk >> 6, c = kk & 63;
        int src = c * K27 + k;
        g_wth[i] = __float2half_rn(w[o * CK + src]);
        g_wt_off_h[i] = (o < OFFC) ? __float2half_rn(w_off[o * CK + src])
                                   : __float2half_rn(0.0f);
    }
    if (i < COUT) { g_sum[i] = 0.0f; g_sqsum[i] = 0.0f; }
}

// ---------------------------------------------------------------------------
// Kernel: deformable (trilinear) im2col gather, fp16 in / fp16 out.
// One block per position; items = (tap, 8-channel group).
// ---------------------------------------------------------------------------
__global__ void __launch_bounds__(128)
deform_gather_kernel() {
    int bn = blockIdx.x;
    int b = bn >= NN;
    int n = bn - b * NN;
    int t = n / (HH * WW);
    int y = (n / WW) % HH;
    int xx = n % WW;

    __shared__ int   s_idx[K27][8];
    __shared__ float s_w[K27][8];

    int tid = threadIdx.x;
    if (tid < K27) {
        int k = tid;
        int kt = k / 9, ky = (k / 3) % 3, kx = k % 3;
        size_t oidx = (size_t)(b * K27 + k) * NN + n;
        float pt = (float)(t + kt - 1) + g_doff[0][oidx];
        float py = (float)(y + ky - 1) + g_doff[1][oidx];
        float px = (float)(xx + kx - 1) + g_doff[2][oidx];
        float tf = floorf(pt), yf = floorf(py), xf = floorf(px);
        int it = (int)tf, iy = (int)yf, ix = (int)xf;
        float ft = pt - tf, fy = py - yf, fx = px - xf;
        #pragma unroll
        for (int j = 0; j < 8; j++) {
            int at = (j >> 2) & 1, ay = (j >> 1) & 1, ax = j & 1;
            int ti = it + at, yi = iy + ay, xi = ix + ax;
            bool valid = (ti >= 0 && ti < TT && yi >= 0 && yi < HH &&
                          xi >= 0 && xi < WW);
            float wv = (at ? ft : 1.0f - ft) * (ay ? fy : 1.0f - fy)
                     * (ax ? fx : 1.0f - fx);
            s_w[k][j]   = valid ? wv : 0.0f;
            s_idx[k][j] = valid ? (ti * HH + yi) * WW + xi : 0;
        }
    }
    __syncthreads();

    const uint4* xb = (const uint4*)(g_xTh + (size_t)b * NN * CIN); // 8 halfs
    uint4* dst = (uint4*)(g_colsh + (size_t)bn * CK);
    #pragma unroll
    for (int i = 0; i < 2; i++) {
        int u = tid + i * 128;
        if (u < K27 * 8) {
            int k = u >> 3, c8 = u & 7;
            float acc[8];
            #pragma unroll
            for (int q = 0; q < 8; q++) acc[q] = 0.0f;
            #pragma unroll
            for (int j = 0; j < 8; j++) {
                float wv = s_w[k][j];
                uint4 v = __ldg(xb + (size_t)s_idx[k][j] * 8 + c8);
                const __half2* hp = (const __half2*)&v;
                #pragma unroll
                for (int q = 0; q < 4; q++) {
                    float2 f = __half22float2(hp[q]);
                    acc[2 * q]     = fmaf(wv, f.x, acc[2 * q]);
                    acc[2 * q + 1] = fmaf(wv, f.y, acc[2 * q + 1]);
                }
            }
            uint4 o;
            __half2* op = (__half2*)&o;
            #pragma unroll
            for (int q = 0; q < 4; q++)
                op[q] = __floats2half2_rn(acc[2 * q], acc[2 * q + 1]);
            dst[k * 8 + c8] = o;
        }
    }
}

// ---------------------------------------------------------------------------
// GEMM: C[128 pos x 96 ch] per CTA, K=1728, fp16 mma.sync m16n8k16.
// cp.async 3-stage pipeline, XOR-swizzled smem, ldmatrix fragments.
// 256 threads = 8 warps 4(M) x 2(N); warp tile 32 x 48.
// Chunk = 64 k-halfs = one tap (128B per smem row).
// MODE 0: A gathered from g_xTh via dense tap shift (cp.async zfill);
//         B = g_wt_off_h; epilogue tanh -> g_doff.
// MODE 1: A = g_colsh; B = g_wth; epilogue -> out + BN atomics.
// ---------------------------------------------------------------------------
template <int MODE>
__global__ void __launch_bounds__(256, 2)
gemm_cp_kernel(const float* __restrict__ b_off, float* __restrict__ out) {
    extern __shared__ char smem_raw[];
    uint32_t smem_base = smem_u32(smem_raw);

    int tid = threadIdx.x;
    int wid = tid >> 5, lane = tid & 31;
    int gid = lane >> 2, tig = lane & 3;
    int warp_m = wid & 3, warp_n = wid >> 2;
    int n0 = blockIdx.x * NTILE;
    int bb = n0 >= NN;

    const __half* Bmat = (MODE == 0) ? g_wt_off_h : g_wth;

    int c4s = tid & 7;     // granule within row (16B = 8 halfs)
    int row0 = tid >> 3;   // 0..31

    // MODE 0: precompute (t,y,x) for this thread's 4 A rows
    int rt_[4], ry_[4], rx_[4];
    if (MODE == 0) {
        #pragma unroll
        for (int i = 0; i < 4; i++) {
            int n = n0 - bb * NN + row0 + i * 32;
            rt_[i] = n / (HH * WW);
            int r = n % (HH * WW);
            ry_[i] = r / WW;
            rx_[i] = r - ry_[i] * WW;
        }
    }

    auto issue = [&](int chunk) {
        uint32_t stage = (uint32_t)(chunk % NSTAGE) * STAGE_BYTES;
        uint32_t Ab = smem_base + stage;
        uint32_t Bb = Ab + A_STAGE_BYTES;
        if (MODE == 0) {
            int tap = chunk;
            int kt = tap / 9;
            int kr = tap - kt * 9;
            int ky = kr / 3, kx = kr - (kr / 3) * 3;
            #pragma unroll
            for (int i = 0; i < 4; i++) {
                int row = row0 + i * 32;
                int zt = rt_[i] + kt - 1, zy = ry_[i] + ky - 1,
                    zx = rx_[i] + kx - 1;
                bool valid = (zt >= 0 && zt < TT && zy >= 0 && zy < HH &&
                              zx >= 0 && zx < WW);
                int idx = valid ? (bb * NN + (zt * HH + zy) * WW + zx) : 0;
                const __half* src = g_xTh + (size_t)idx * CIN + c4s * 8;
                uint32_t dst = Ab + (row << 7) + ((c4s ^ (row & 7)) << 4);
                cp16(dst, src, valid ? 16 : 0);
            }
        } else {
            #pragma unroll
            for (int i = 0; i < 4; i++) {
                int row = row0 + i * 32;
                const __half* src = g_colsh + (size_t)(n0 + row) * CK
                                  + chunk * 64 + c4s * 8;
                uint32_t dst = Ab + (row << 7) + ((c4s ^ (row & 7)) << 4);
                cp16(dst, src, 16);
            }
        }
        #pragma unroll
        for (int i = 0; i < 3; i++) {
            int col = row0 + i * 32;
            const __half* src = Bmat + (size_t)col * CK + chunk * 64 + c4s * 8;
            uint32_t dst = Bb + (col << 7) + ((c4s ^ (col & 7)) << 4);
            cp16(dst, src, 16);
        }
        CP_COMMIT();
    };

    // accumulators: 2 M-blocks x 6 N-blocks
    float d[2][6][4];
    #pragma unroll
    for (int mt = 0; mt < 2; mt++)
        #pragma unroll
        for (int nt = 0; nt < 6; nt++)
            #pragma unroll
            for (int q = 0; q < 4; q++) d[mt][nt][q] = 0.0f;

    // fragment-load lane geometry
    int a_row_lo = lane & 15;
    int a_hi = lane >> 4;          // granule parity (k-half)
    int b_col = warp_n * 48 + (lane & 7);
    int b_hi = (lane >> 3) & 1;

    issue(0);
    issue(1);

    for (int chunk = 0; chunk < NCHUNK; chunk++) {
        if (chunk < NCHUNK - 1) { CP_WAIT1(); } else { CP_WAIT0(); }
        __syncthreads();
        if (chunk + 2 < NCHUNK) issue(chunk + 2);

        uint32_t stage = (uint32_t)(chunk % NSTAGE) * STAGE_BYTES;
        uint32_t Ab = smem_base + stage;
        uint32_t Bb = Ab + A_STAGE_BYTES;

        #pragma unroll
        for (int ks = 0; ks < 4; ks++) {   // 4 k16-steps per 64-half chunk
            uint32_t af[2][4], bf[6][2];
            #pragma unroll
            for (int mt = 0; mt < 2; mt++) {
                int row = warp_m * 32 + mt * 16 + a_row_lo;
                int g = 2 * ks + a_hi;
                uint32_t addr = Ab + (row << 7) + ((g ^ (row & 7)) << 4);
                ldsm_x4(af[mt], addr);
            }
            #pragma unroll
            for (int nt = 0; nt < 6; nt++) {
                int col = b_col + nt * 8;
                int g = 2 * ks + b_hi;
                uint32_t addr = Bb + (col << 7) + ((g ^ (col & 7)) << 4);
                ldsm_x2(bf[nt], addr);
            }
            #pragma unroll
            for (int mt = 0; mt < 2; mt++)
                #pragma unroll
                for (int nt = 0; nt < 6; nt++)
                    mma_f16(d[mt][nt], af[mt], bf[nt]);
        }
        __syncthreads();
    }

    // ---- epilogue ------------------------------------------------------
    #pragma unroll
    for (int mt = 0; mt < 2; mt++) {
        #pragma unroll
        for (int half = 0; half < 2; half++) {
            int row = warp_m * 32 + mt * 16 + half * 8 + gid;
            int n = n0 - bb * NN + row;
            #pragma unroll
            for (int nt = 0; nt < 6; nt++) {
                #pragma unroll
                for (int e = 0; e < 2; e++) {
                    int col = warp_n * 48 + nt * 8 + tig * 2 + e;
                    float v = d[mt][nt][half * 2 + e];
                    if (MODE == 0) {
                        if (col < OFFC) {
                            int axis = col / K27, kk = col - axis * K27;
                            float sc = axis ? 2.0f : 1.0f;
                            float o = tanhf(v + __ldg(b_off + col)) * sc;
                            g_doff[axis][(size_t)(bb * K27 + kk) * NN + n] = o;
                        }
                    } else {
                        out[(size_t)(bb * COUT + col) * NN + n] = v;
                    }
                }
            }
        }
    }

    // ---- fused BN stats (MODE 1) ---------------------------------------
    if (MODE == 1) {
        #pragma unroll
        for (int nt = 0; nt < 6; nt++) {
            #pragma unroll
            for (int e = 0; e < 2; e++) {
                float s = 0.0f, q = 0.0f;
                #pragma unroll
                for (int mt = 0; mt < 2; mt++)
                    #pragma unroll
                    for (int half = 0; half < 2; half++) {
                        float v = d[mt][nt][half * 2 + e];
                        s += v; q += v * v;
                    }
                #pragma unroll
                for (int off = 16; off >= 4; off >>= 1) {
                    s += __shfl_down_sync(0xffffffffu, s, off);
                    q += __shfl_down_sync(0xffffffffu, q, off);
                }
                if (lane < 4) {
                    int col = warp_n * 48 + nt * 8 + tig * 2 + e;
                    atomicAdd(&g_sum[col], s);
                    atomicAdd(&g_sqsum[col], q);
                }
            }
        }
    }
}

// ---------------------------------------------------------------------------
// BN finalize + apply
// ---------------------------------------------------------------------------
__global__ void bn_finalize_kernel(const float* __restrict__ gamma,
                                   const float* __restrict__ beta) {
    int c = threadIdx.x;
    if (c < COUT) {
        float cnt = (float)(BB * NN);
        float mean = g_sum[c] / cnt;
        float var = g_sqsum[c] / cnt - mean * mean;
        float inv = rsqrtf(var + 1e-5f);
        float sc = gamma[c] * inv;
        g_scale[c] = sc;
        g_bias[c] = beta[c] - mean * sc;
    }
}

__global__ void __launch_bounds__(256)
bn_apply_kernel(float* __restrict__ out) {
    int i4 = blockIdx.x * blockDim.x + threadIdx.x;
    const int TOT4 = BB * COUT * NN / 4;
    if (i4 < TOT4) {
        int c = (i4 / (NN / 4)) % COUT;
        float sc = g_scale[c], bi = g_bias[c];
        float4 v = reinterpret_cast<float4*>(out)[i4];
        v.x = fmaxf(fmaf(v.x, sc, bi), 0.0f);
        v.y = fmaxf(fmaf(v.y, sc, bi), 0.0f);
        v.z = fmaxf(fmaf(v.z, sc, bi), 0.0f);
        v.w = fmaxf(fmaf(v.w, sc, bi), 0.0f);
        reinterpret_cast<float4*>(out)[i4] = v;
    }
}

// ---------------------------------------------------------------------------
extern "C" void kernel_launch(void* const* d_in, const int* in_sizes, int n_in,
                              void* d_out, int out_size) {
    const float* x     = (const float*)d_in[0];
    const float* w_off = (const float*)d_in[1];
    const float* b_off = (const float*)d_in[2];
    const float* w     = (const float*)d_in[3];
    const float* gamma = (const float*)d_in[4];
    const float* beta  = (const float*)d_in[5];
    float* out = (float*)d_out;

    cudaFuncSetAttribute(gemm_cp_kernel<0>,
                         cudaFuncAttributeMaxDynamicSharedMemorySize,
                         SMEM_BYTES);
    cudaFuncSetAttribute(gemm_cp_kernel<1>,
                         cudaFuncAttributeMaxDynamicSharedMemorySize,
                         SMEM_BYTES);

    transpose_kernel<<<BN_TOT / 32, dim3(32, 8)>>>(x);
    prep_kernel<<<(96 * CK + 255) / 256, 256>>>(w_off, w);

    gemm_cp_kernel<0><<<NTILES, 256, SMEM_BYTES>>>(b_off, nullptr);
    deform_gather_kernel<<<BN_TOT, 128>>>();
    gemm_cp_kernel<1><<<NTILES, 256, SMEM_BYTES>>>(nullptr, out);

    bn_finalize_kernel<<<1, 128>>>(gamma, beta);

    const int TOT4 = BB * COUT * NN / 4;
    bn_apply_kernel<<<(TOT4 + 255) / 256, 256>>>(out);
}